// round 4
// baseline (speedup 1.0000x reference)
#include <cuda_runtime.h>

// Problem constants (fixed by the dataset)
#define NB       2        // batch
#define SDIM     256      // S
#define FDIM     512      // F1 = F2
#define NNODES   20000    // N
#define NE_      320000   // E
#define NLAYERS  3
#define BSJ      512      // NB * SDIM

// ---------------- scratch (device globals; no runtime allocation) ----------
__device__ float g_nsum[(size_t)NNODES * FDIM];        // 41 MB
__device__ float g_CT  [(size_t)BSJ * FDIM];           // 1 MB
__device__ float g_WpT [(size_t)FDIM * FDIM];          // 1 MB  Wp^T [f2][k]
__device__ float g_dvec[BSJ];
__device__ float g_hA  [(size_t)NB * NNODES * SDIM];   // 41 MB (h)
__device__ float g_hB  [(size_t)NB * NNODES * SDIM];   // 41 MB (hw)
__device__ float g_WT  [(size_t)NLAYERS * SDIM * SDIM];// transposed layer weights
__device__ int   g_deg [NNODES];
__device__ int   g_off [NNODES + 1];
__device__ int   g_cur [NNODES];
__device__ int   g_srcs[NE_];
__device__ float g_dinv[NNODES];

// ---------------- CSR build ------------------------------------------------
__global__ void k_init_deg() {
    int i = blockIdx.x * blockDim.x + threadIdx.x;
    if (i < NNODES) g_deg[i] = 1;
}

__global__ void k_hist(const int* __restrict__ ei) {
    int e = blockIdx.x * blockDim.x + threadIdx.x;
    if (e < NE_) atomicAdd(&g_deg[ei[NE_ + e]], 1);
}

__global__ void k_scan() {
    __shared__ int ssum[512];
    int tid = threadIdx.x;
    const int CH = (NNODES + 511) / 512;
    int base = tid * CH;
    int s = 0;
    for (int i = 0; i < CH; ++i) {
        int idx = base + i;
        if (idx < NNODES) s += g_deg[idx] - 1;
    }
    ssum[tid] = s;
    __syncthreads();
    for (int off = 1; off < 512; off <<= 1) {
        int v = ssum[tid];
        int u = (tid >= off) ? ssum[tid - off] : 0;
        __syncthreads();
        ssum[tid] = v + u;
        __syncthreads();
    }
    int run = (tid == 0) ? 0 : ssum[tid - 1];
    for (int i = 0; i < CH; ++i) {
        int idx = base + i;
        if (idx < NNODES) {
            g_off[idx] = run;
            g_cur[idx] = run;
            g_dinv[idx] = rsqrtf((float)g_deg[idx]);
            run += g_deg[idx] - 1;
        }
    }
    if (tid == 511) g_off[NNODES] = run;
}

__global__ void k_scatter(const int* __restrict__ ei) {
    int e = blockIdx.x * blockDim.x + threadIdx.x;
    if (e < NE_) {
        int d = ei[NE_ + e];
        int p = atomicAdd(&g_cur[d], 1);
        g_srcs[p] = ei[e];
    }
}

// ---------------- nsum[n,f] = nodes[n,0,f] + nodes[n,1,f] ------------------
__global__ void k_nsum(const float* __restrict__ nodes) {
    long i = (long)blockIdx.x * blockDim.x + threadIdx.x;
    const long total = (long)NNODES * FDIM / 4;
    if (i >= total) return;
    const float4* nd = (const float4*)nodes;
    float4* ns = (float4*)g_nsum;
    long n = i / (FDIM / 4);
    long f = i % (FDIM / 4);
    float4 a = nd[n * (2 * FDIM / 4) + f];
    float4 b = nd[n * (2 * FDIM / 4) + FDIM / 4 + f];
    ns[i] = make_float4(a.x + b.x, a.y + b.y, a.z + b.z, a.w + b.w);
}

// ---------------- dvec[j] = 2 * sum_k bp[k]*x[j,k] -------------------------
__global__ void k_dvec(const float* __restrict__ x, const float* __restrict__ bp) {
    __shared__ float sh[256];
    int j = blockIdx.x;
    float s = 0.f;
    for (int k = threadIdx.x; k < FDIM; k += 256)
        s += bp[k] * x[(long)j * FDIM + k];
    sh[threadIdx.x] = s;
    __syncthreads();
    for (int o = 128; o > 0; o >>= 1) {
        if (threadIdx.x < o) sh[threadIdx.x] += sh[threadIdx.x + o];
        __syncthreads();
    }
    if (threadIdx.x == 0) g_dvec[j] = 2.f * sh[0];
}

// ---------------- weight transposes ----------------------------------------
__global__ void k_wt(const float* __restrict__ gW) {
    int idx = blockIdx.x * blockDim.x + threadIdx.x;
    if (idx >= NLAYERS * SDIM * SDIM) return;
    int l = idx / (SDIM * SDIM);
    int r = idx % (SDIM * SDIM);
    int i = r >> 8, o = r & 255;
    g_WT[(long)l * SDIM * SDIM + o * SDIM + i] = gW[idx];
}

__global__ void k_wpT(const float* __restrict__ Wp) {
    int idx = blockIdx.x * blockDim.x + threadIdx.x;
    if (idx >= FDIM * FDIM) return;
    int k = idx / FDIM, f2 = idx % FDIM;
    g_WpT[(long)f2 * FDIM + k] = Wp[idx];
}

// ---------------- TF32 tensor-core NT GEMM (3xTF32 split) ------------------
// C[M,N] = A[M,K] * B[N,K]^T ; 128x128 tile, KSTEP=16, 8 warps, 64x32 warp
// tiles, cp.async double-buffered, hi/lo split in registers.
__device__ __forceinline__ float tf32f(float x) {
    unsigned r;
    asm("cvt.rna.tf32.f32 %0, %1;" : "=r"(r) : "f"(x));
    return __uint_as_float(r);
}

__device__ __forceinline__ void mma8(float c[4], const unsigned a[4], const unsigned b[2]) {
    asm volatile(
        "mma.sync.aligned.m16n8k8.row.col.f32.tf32.tf32.f32 "
        "{%0,%1,%2,%3}, {%4,%5,%6,%7}, {%8,%9}, {%0,%1,%2,%3};"
        : "+f"(c[0]), "+f"(c[1]), "+f"(c[2]), "+f"(c[3])
        : "r"(a[0]), "r"(a[1]), "r"(a[2]), "r"(a[3]), "r"(b[0]), "r"(b[1]));
}

__device__ __forceinline__ void cpasync16(float* dst, const float* src, int nbytes) {
    unsigned d = (unsigned)__cvta_generic_to_shared(dst);
    asm volatile("cp.async.cg.shared.global [%0], [%1], 16, %2;\n"
                 :: "r"(d), "l"(src), "r"(nbytes));
}

#define KST  16   // K per mainloop iteration
#define ASTR 20   // smem row stride in floats (80B: 16B-multiple, conflict-free)

__global__ __launch_bounds__(256) void mma_nt(
    const float* __restrict__ A, const float* __restrict__ B, float* __restrict__ Cout,
    int M, int N, int K, long sA, long sC, int h0, const float* __restrict__ dvec)
{
    A += (long)blockIdx.z * sA;
    __shared__ float As[2][128 * ASTR];
    __shared__ float Bs[2][128 * ASTR];
    int t = threadIdx.x;
    int brow = blockIdx.x * 128, bcol = blockIdx.y * 128;
    int lane = t & 31, wid = t >> 5;
    int g = lane >> 2, tig = lane & 3;
    int wm = (wid & 1) * 64, wn = (wid >> 1) * 32;

    // cp.async: 512 16B-chunks per tile; thread t handles chunks t and t+256.
    int r0c = t >> 2, q0 = (t & 3) * 4;          // chunk t  : row t>>2, quad t&3
    int r1c = r0c + 64;                           // chunk t+256
    const float* Asrc0 = A + (long)(brow + r0c) * K + q0;
    const float* Asrc1 = A + (long)(brow + r1c) * K + q0;
    const float* Bsrc0 = B + (long)(bcol + r0c) * K + q0;
    const float* Bsrc1 = B + (long)(bcol + r1c) * K + q0;
    int av0 = ((brow + r0c) < M) ? 16 : 0;
    int av1 = ((brow + r1c) < M) ? 16 : 0;
    int d0 = r0c * ASTR + q0;
    int d1 = r1c * ASTR + q0;

    float acc[4][4][4] = {};
    int nK = K / KST;

    cpasync16(&As[0][d0], Asrc0, av0);
    cpasync16(&As[0][d1], Asrc1, av1);
    cpasync16(&Bs[0][d0], Bsrc0, 16);
    cpasync16(&Bs[0][d1], Bsrc1, 16);
    asm volatile("cp.async.commit_group;\n");

    for (int it = 0; it < nK; ++it) {
        asm volatile("cp.async.wait_group 0;\n");
        __syncthreads();
        if (it + 1 < nK) {
            int s = (it + 1) & 1;
            int ko = (it + 1) * KST;
            cpasync16(&As[s][d0], Asrc0 + ko, av0);
            cpasync16(&As[s][d1], Asrc1 + ko, av1);
            cpasync16(&Bs[s][d0], Bsrc0 + ko, 16);
            cpasync16(&Bs[s][d1], Bsrc1 + ko, 16);
            asm volatile("cp.async.commit_group;\n");
        }
        const float* as = As[it & 1];
        const float* bs = Bs[it & 1];

#pragma unroll
        for (int ks = 0; ks < KST; ks += 8) {
            unsigned ah[4][4], al[4][4], bh[4][2], bl[4][2];
#pragma unroll
            for (int mi = 0; mi < 4; ++mi) {
                int m = wm + mi * 16 + g;
                float r0 = as[m * ASTR + ks + tig];
                float r1 = as[(m + 8) * ASTR + ks + tig];
                float r2 = as[m * ASTR + ks + tig + 4];
                float r3 = as[(m + 8) * ASTR + ks + tig + 4];
                float h0v = tf32f(r0), h1v = tf32f(r1), h2v = tf32f(r2), h3v = tf32f(r3);
                ah[mi][0] = __float_as_uint(h0v); al[mi][0] = __float_as_uint(r0 - h0v);
                ah[mi][1] = __float_as_uint(h1v); al[mi][1] = __float_as_uint(r1 - h1v);
                ah[mi][2] = __float_as_uint(h2v); al[mi][2] = __float_as_uint(r2 - h2v);
                ah[mi][3] = __float_as_uint(h3v); al[mi][3] = __float_as_uint(r3 - h3v);
            }
#pragma unroll
            for (int ni = 0; ni < 4; ++ni) {
                int n = wn + ni * 8 + g;
                float r0 = bs[n * ASTR + ks + tig];
                float r1 = bs[n * ASTR + ks + tig + 4];
                float h0v = tf32f(r0), h1v = tf32f(r1);
                bh[ni][0] = __float_as_uint(h0v); bl[ni][0] = __float_as_uint(r0 - h0v);
                bh[ni][1] = __float_as_uint(h1v); bl[ni][1] = __float_as_uint(r1 - h1v);
            }
#pragma unroll
            for (int mi = 0; mi < 4; ++mi)
#pragma unroll
                for (int ni = 0; ni < 4; ++ni) {
                    mma8(acc[mi][ni], ah[mi], bh[ni]);
                    mma8(acc[mi][ni], ah[mi], bl[ni]);
                    mma8(acc[mi][ni], al[mi], bh[ni]);
                }
        }
    }

    // epilogue
    if (!h0) {
        float* C = Cout + (long)blockIdx.z * sC;
#pragma unroll
        for (int mi = 0; mi < 4; ++mi) {
            int r0 = brow + wm + mi * 16 + g;
#pragma unroll
            for (int ni = 0; ni < 4; ++ni) {
                int c0 = bcol + wn + ni * 8 + 2 * tig;
                if (r0 < M) {
                    C[(long)r0 * N + c0]     = acc[mi][ni][0];
                    C[(long)r0 * N + c0 + 1] = acc[mi][ni][1];
                }
                if (r0 + 8 < M) {
                    C[(long)(r0 + 8) * N + c0]     = acc[mi][ni][2];
                    C[(long)(r0 + 8) * N + c0 + 1] = acc[mi][ni][3];
                }
            }
        }
    } else {
        int b = bcol >> 8;
        float* C = Cout + (long)b * NNODES * SDIM;
#pragma unroll
        for (int mi = 0; mi < 4; ++mi) {
            int r0 = brow + wm + mi * 16 + g;
#pragma unroll
            for (int ni = 0; ni < 4; ++ni) {
                int c0 = bcol + wn + ni * 8 + 2 * tig;
                int s0 = c0 & 255;
                float dd0 = dvec[c0], dd1 = dvec[c0 + 1];
                if (r0 < M) {
                    float* p = C + (long)r0 * SDIM + s0;
                    p[0] = acc[mi][ni][0] + dd0;
                    p[1] = acc[mi][ni][1] + dd1;
                }
                if (r0 + 8 < M) {
                    float* p = C + (long)(r0 + 8) * SDIM + s0;
                    p[0] = acc[mi][ni][2] + dd0;
                    p[1] = acc[mi][ni][3] + dd1;
                }
            }
        }
    }
}

// ---------------- CSR aggregation + bias + leaky relu (float4) -------------
// 256 threads = 4 nodes per block; 64 threads per (node,batch) row.
__global__ __launch_bounds__(256) void k_agg(const float* __restrict__ bias) {
    int node = blockIdx.x * 4 + (threadIdx.x >> 6);
    int b = blockIdx.y;
    int tid = threadIdx.x & 63;
    float dt = g_dinv[node];
    long base4 = (long)b * NNODES * (SDIM / 4);
    const float4* hB4 = (const float4*)g_hB + base4;
    float4* hA4 = (float4*)g_hA + base4;

    float4 v = hB4[(long)node * 64 + tid];
    float sw = dt * dt;
    float4 acc = make_float4(v.x * sw, v.y * sw, v.z * sw, v.w * sw);
    int e0 = g_off[node], e1 = g_off[node + 1];
    for (int e = e0; e < e1; ++e) {
        int src = g_srcs[e];
        float w = g_dinv[src] * dt;
        float4 u = hB4[(long)src * 64 + tid];
        acc.x = fmaf(u.x, w, acc.x);
        acc.y = fmaf(u.y, w, acc.y);
        acc.z = fmaf(u.z, w, acc.z);
        acc.w = fmaf(u.w, w, acc.w);
    }
    float4 bb = ((const float4*)bias)[tid];
    acc.x += bb.x; acc.y += bb.y; acc.z += bb.z; acc.w += bb.w;
    acc.x = acc.x > 0.f ? acc.x : 0.01f * acc.x;
    acc.y = acc.y > 0.f ? acc.y : 0.01f * acc.y;
    acc.z = acc.z > 0.f ? acc.z : 0.01f * acc.z;
    acc.w = acc.w > 0.f ? acc.w : 0.01f * acc.w;
    hA4[(long)node * 64 + tid] = acc;
}

// ---------------- output: out[b,n] = sum_s h[b,n,s]*wbp[s] + bbp -----------
__global__ void k_out(const float* __restrict__ wbp, const float* __restrict__ bbp,
                      float* __restrict__ out) {
    int gw = (blockIdx.x * blockDim.x + threadIdx.x) >> 5;
    int lane = threadIdx.x & 31;
    if (gw >= NB * NNODES) return;
    int b = gw / NNODES, n = gw % NNODES;
    const float4* hr = (const float4*)(g_hA + ((long)b * NNODES + n) * SDIM);
    const float4* w4 = (const float4*)wbp;
    float s = 0.f;
#pragma unroll
    for (int k = lane; k < SDIM / 4; k += 32) {
        float4 h = hr[k];
        float4 w = w4[k];
        s = fmaf(h.x, w.x, s);
        s = fmaf(h.y, w.y, s);
        s = fmaf(h.z, w.z, s);
        s = fmaf(h.w, w.w, s);
    }
#pragma unroll
    for (int o = 16; o; o >>= 1) s += __shfl_xor_sync(0xffffffffu, s, o);
    if (lane == 0) out[(long)b * NNODES + n] = s + bbp[0];
}

// ---------------- launcher -------------------------------------------------
extern "C" void kernel_launch(void* const* d_in, const int* in_sizes, int n_in,
                              void* d_out, int out_size) {
    const float* x     = (const float*)d_in[0];
    const float* nodes = (const float*)d_in[1];
    const int*   ei    = (const int*)  d_in[2];
    const float* Wp    = (const float*)d_in[3];
    const float* bp    = (const float*)d_in[4];
    const float* gW    = (const float*)d_in[5];
    const float* gb    = (const float*)d_in[6];
    const float* wbp   = (const float*)d_in[7];
    const float* bbp   = (const float*)d_in[8];
    float* out = (float*)d_out;

    void *pCT, *pHA, *pHB, *pNS, *pWT, *pDV, *pWpT;
    cudaGetSymbolAddress(&pCT, g_CT);
    cudaGetSymbolAddress(&pHA, g_hA);
    cudaGetSymbolAddress(&pHB, g_hB);
    cudaGetSymbolAddress(&pNS, g_nsum);
    cudaGetSymbolAddress(&pWT, g_WT);
    cudaGetSymbolAddress(&pDV, g_dvec);
    cudaGetSymbolAddress(&pWpT, g_WpT);
    float* CTp = (float*)pCT;
    float* hAp = (float*)pHA;
    float* hBp = (float*)pHB;
    float* NSp = (float*)pNS;
    float* WTp = (float*)pWT;
    float* DVp = (float*)pDV;
    float* WpTp = (float*)pWpT;

    const int MB = (NNODES + 127) / 128;   // 157

    // ---- front-end first (puts big GEMMs at launch indices 4 and 5 for ncu)
    k_nsum<<<(int)(((long)NNODES * FDIM / 4 + 255) / 256), 256>>>(nodes);   // 0
    k_wpT<<<(FDIM * FDIM + 255) / 256, 256>>>(Wp);                           // 1
    k_dvec<<<BSJ, 256>>>(x, bp);                                             // 2
    k_wt<<<(NLAYERS * SDIM * SDIM + 255) / 256, 256>>>(gW);                  // 3

    // CT[j,f2] = sum_k x[j,k]*Wp[k,f2]
    mma_nt<<<dim3(BSJ / 128, FDIM / 128, 1), 256>>>(x, WpTp, CTp,            // 4
                                                    BSJ, FDIM, FDIM, 0, 0, 0, nullptr);
    // H0: h = nsum @ CT^T + dvec -> g_hA
    mma_nt<<<dim3(MB, BSJ / 128, 1), 256>>>(NSp, CTp, hAp,                   // 5
                                            NNODES, BSJ, FDIM, 0, 0, 1, DVp);

    // ---- CSR build (only needed before first k_agg)
    k_init_deg<<<(NNODES + 255) / 256, 256>>>();
    k_hist<<<(NE_ + 255) / 256, 256>>>(ei);
    k_scan<<<1, 512>>>();
    k_scatter<<<(NE_ + 255) / 256, 256>>>(ei);

    // ---- GCN layers
    const long slab = (long)NNODES * SDIM;
    for (int l = 0; l < NLAYERS; ++l) {
        mma_nt<<<dim3(MB, SDIM / 128, NB), 256>>>(
            hAp, WTp + (long)l * SDIM * SDIM, hBp,
            NNODES, SDIM, SDIM, slab, slab, 0, nullptr);
        k_agg<<<dim3(NNODES / 4, NB), 256>>>(gb + (long)l * SDIM);
    }

    // ---- belief projection
    k_out<<<(NB * NNODES * 32 + 255) / 256, 256>>>(wbp, bbp, out);
}

// round 6
// speedup vs baseline: 1.5099x; 1.5099x over previous
#include <cuda_runtime.h>
#include <cuda_bf16.h>
#include <cstdint>

#define NB       2
#define SDIM     256
#define FDIM     512
#define NNODES   20000
#define NE_      320000
#define NLAYERS  3
#define BSJ      512

// ---------------- scratch (device globals) ---------------------------------
__device__ __nv_bfloat16 g_nsum_hi[(size_t)NNODES * FDIM];
__device__ __nv_bfloat16 g_nsum_lo[(size_t)NNODES * FDIM];
__device__ __nv_bfloat16 g_x_hi  [(size_t)BSJ * FDIM];
__device__ __nv_bfloat16 g_x_lo  [(size_t)BSJ * FDIM];
__device__ __nv_bfloat16 g_WpT_hi[(size_t)FDIM * FDIM];
__device__ __nv_bfloat16 g_WpT_lo[(size_t)FDIM * FDIM];
__device__ __nv_bfloat16 g_CT_hi [(size_t)BSJ * FDIM];
__device__ __nv_bfloat16 g_CT_lo [(size_t)BSJ * FDIM];
__device__ __nv_bfloat16 g_WT_hi [(size_t)NLAYERS * SDIM * SDIM];
__device__ __nv_bfloat16 g_WT_lo [(size_t)NLAYERS * SDIM * SDIM];
__device__ __nv_bfloat16 g_Ahi   [(size_t)NB * NNODES * SDIM];   // h hi
__device__ __nv_bfloat16 g_Alo   [(size_t)NB * NNODES * SDIM];   // h lo
__device__ float g_hB  [(size_t)NB * NNODES * SDIM];             // hw fp32
__device__ float g_dvec[BSJ];
__device__ int   g_deg [NNODES];
__device__ int   g_off [NNODES + 1];
__device__ int   g_cur [NNODES];
__device__ int   g_srcs[NE_];
__device__ float g_dinv[NNODES];

__device__ __forceinline__ void bsplit(float v, __nv_bfloat16& h, __nv_bfloat16& l) {
    h = __float2bfloat16(v);
    l = __float2bfloat16(v - __bfloat162float(h));
}

// ---------------- CSR build ------------------------------------------------
__global__ void k_init_deg() {
    int i = blockIdx.x * blockDim.x + threadIdx.x;
    if (i < NNODES) g_deg[i] = 1;
}
__global__ void k_hist(const int* __restrict__ ei) {
    int e = blockIdx.x * blockDim.x + threadIdx.x;
    if (e < NE_) atomicAdd(&g_deg[ei[NE_ + e]], 1);
}
__global__ void k_scan() {
    __shared__ int ssum[512];
    int tid = threadIdx.x;
    const int CH = (NNODES + 511) / 512;
    int base = tid * CH;
    int s = 0;
    for (int i = 0; i < CH; ++i) {
        int idx = base + i;
        if (idx < NNODES) s += g_deg[idx] - 1;
    }
    ssum[tid] = s;
    __syncthreads();
    for (int off = 1; off < 512; off <<= 1) {
        int v = ssum[tid];
        int u = (tid >= off) ? ssum[tid - off] : 0;
        __syncthreads();
        ssum[tid] = v + u;
        __syncthreads();
    }
    int run = (tid == 0) ? 0 : ssum[tid - 1];
    for (int i = 0; i < CH; ++i) {
        int idx = base + i;
        if (idx < NNODES) {
            g_off[idx] = run;
            g_cur[idx] = run;
            g_dinv[idx] = rsqrtf((float)g_deg[idx]);
            run += g_deg[idx] - 1;
        }
    }
    if (tid == 511) g_off[NNODES] = run;
}
__global__ void k_scatter(const int* __restrict__ ei) {
    int e = blockIdx.x * blockDim.x + threadIdx.x;
    if (e < NE_) {
        int d = ei[NE_ + e];
        int p = atomicAdd(&g_cur[d], 1);
        g_srcs[p] = ei[e];
    }
}

// ---------------- nsum -> bf16 hi/lo ---------------------------------------
__global__ void k_nsum(const float* __restrict__ nodes) {
    long i = (long)blockIdx.x * blockDim.x + threadIdx.x;
    const long total = (long)NNODES * FDIM / 4;
    if (i >= total) return;
    const float4* nd = (const float4*)nodes;
    long n = i / (FDIM / 4);
    long f = i % (FDIM / 4);
    float4 a = nd[n * (2 * FDIM / 4) + f];
    float4 b = nd[n * (2 * FDIM / 4) + FDIM / 4 + f];
    float v[4] = {a.x + b.x, a.y + b.y, a.z + b.z, a.w + b.w};
    __nv_bfloat16 h[4], l[4];
#pragma unroll
    for (int q = 0; q < 4; ++q) bsplit(v[q], h[q], l[q]);
    __nv_bfloat162* ph = (__nv_bfloat162*)g_nsum_hi + i * 2;
    __nv_bfloat162* pl = (__nv_bfloat162*)g_nsum_lo + i * 2;
    ph[0] = __nv_bfloat162{h[0], h[1]}; ph[1] = __nv_bfloat162{h[2], h[3]};
    pl[0] = __nv_bfloat162{l[0], l[1]}; pl[1] = __nv_bfloat162{l[2], l[3]};
}

// ---------------- prep: x cvt, WpT, WT transposes, dvec --------------------
#define PREP_S0 1024
#define PREP_S1 1024
#define PREP_S2 768
__global__ void k_prep(const float* __restrict__ x, const float* __restrict__ Wp,
                       const float* __restrict__ gW, const float* __restrict__ bp) {
    int blk = blockIdx.x;
    if (blk < PREP_S0) {
        int idx = blk * 256 + threadIdx.x;
        bsplit(x[idx], g_x_hi[idx], g_x_lo[idx]);
    } else if (blk < PREP_S0 + PREP_S1) {
        int idx = (blk - PREP_S0) * 256 + threadIdx.x;
        int k = idx >> 9, f2 = idx & 511;
        bsplit(Wp[idx], g_WpT_hi[(long)f2 * FDIM + k], g_WpT_lo[(long)f2 * FDIM + k]);
    } else if (blk < PREP_S0 + PREP_S1 + PREP_S2) {
        int idx = (blk - PREP_S0 - PREP_S1) * 256 + threadIdx.x;
        int l = idx / (SDIM * SDIM), r2 = idx % (SDIM * SDIM);
        int i = r2 >> 8, o = r2 & 255;
        long dst = (long)l * SDIM * SDIM + (long)o * SDIM + i;
        bsplit(gW[idx], g_WT_hi[dst], g_WT_lo[dst]);
    } else {
        __shared__ float sh[256];
        int j = blk - (PREP_S0 + PREP_S1 + PREP_S2);
        float s = 0.f;
        for (int k = threadIdx.x; k < FDIM; k += 256)
            s += bp[k] * x[(long)j * FDIM + k];
        sh[threadIdx.x] = s;
        __syncthreads();
        for (int o = 128; o > 0; o >>= 1) {
            if (threadIdx.x < o) sh[threadIdx.x] += sh[threadIdx.x + o];
            __syncthreads();
        }
        if (threadIdx.x == 0) g_dvec[j] = 2.f * sh[0];
    }
}

// ---------------- bf16-split NT GEMM via mma.sync.m16n8k16 -----------------
// C[M,N] = A[M,K] * B[N,K]^T, operands bf16 hi/lo pairs, 3-term split.
// 128x128 tile, KSTEP=32, 8 warps (2x4), 64x32 warp tiles, cp.async 2-stage.
// modes: 0 = fp32 store (ldc); 1 = H0 (dvec add + split [b,n,s]); 2 = split row-major.
#define KST   32
#define RSTR  40                     // bf16 per smem row (80 B, conflict-free)
#define TILEB (128 * RSTR * 2)       // 10240 B per tile buffer
#define MMA_SMEM (8 * TILEB)         // 81920 B

__device__ __forceinline__ void cpa16g(void* dst, const void* src, int nbytes) {
    unsigned d = (unsigned)__cvta_generic_to_shared(dst);
    asm volatile("cp.async.cg.shared.global [%0], [%1], 16, %2;\n"
                 :: "r"(d), "l"(src), "r"(nbytes));
}
__device__ __forceinline__ void mma16(float c[4], const unsigned a[4], const unsigned b[2]) {
    asm volatile(
        "mma.sync.aligned.m16n8k16.row.col.f32.bf16.bf16.f32 "
        "{%0,%1,%2,%3}, {%4,%5,%6,%7}, {%8,%9}, {%0,%1,%2,%3};"
        : "+f"(c[0]), "+f"(c[1]), "+f"(c[2]), "+f"(c[3])
        : "r"(a[0]), "r"(a[1]), "r"(a[2]), "r"(a[3]), "r"(b[0]), "r"(b[1]));
}
__device__ __forceinline__ void store_split(__nv_bfloat16* Ohi, __nv_bfloat16* Olo,
                                            long idx, float v0, float v1) {
    __nv_bfloat16 h0, l0, h1, l1;
    bsplit(v0, h0, l0);
    bsplit(v1, h1, l1);
    *(__nv_bfloat162*)(Ohi + idx) = __nv_bfloat162{h0, h1};
    *(__nv_bfloat162*)(Olo + idx) = __nv_bfloat162{l0, l1};
}

__global__ __launch_bounds__(256) void mma_bf(
    const __nv_bfloat16* __restrict__ Ahi, const __nv_bfloat16* __restrict__ Alo,
    const __nv_bfloat16* __restrict__ Bhi, const __nv_bfloat16* __restrict__ Blo,
    float* __restrict__ C, __nv_bfloat16* __restrict__ Ohi, __nv_bfloat16* __restrict__ Olo,
    const float* __restrict__ dvec,
    int M, int K, int ldc, long aSlab, long cSlab, int mode)
{
    extern __shared__ char smem[];
    int t = threadIdx.x;
    int brow = blockIdx.x * 128, bcol = blockIdx.y * 128;
    long zA = (long)blockIdx.z * aSlab;
    int lane = t & 31, wid = t >> 5;
    int g = lane >> 2, tig = lane & 3;
    int wm = (wid & 1) * 64, wn = (wid >> 1) * 32;

    float acc[4][4][4] = {};
    int nK = K / KST;

    auto load_stage = [&](int st, int k0) {
        char* base = smem + st * 4 * TILEB;
#pragma unroll
        for (int half = 0; half < 2; ++half) {
            int c = t + half * 256;
            int row = c >> 2, q = c & 3;
            long ao = zA + (long)(brow + row) * K + k0 + q * 8;
            long bo = (long)(bcol + row) * K + k0 + q * 8;
            int av = ((brow + row) < M) ? 16 : 0;
            unsigned off = row * (RSTR * 2) + q * 16;
            cpa16g(base + 0 * TILEB + off, Ahi + ao, av);
            cpa16g(base + 1 * TILEB + off, Alo + ao, av);
            cpa16g(base + 2 * TILEB + off, Bhi + bo, 16);
            cpa16g(base + 3 * TILEB + off, Blo + bo, 16);
        }
        asm volatile("cp.async.commit_group;\n");
    };

    load_stage(0, 0);

    for (int it = 0; it < nK; ++it) {
        asm volatile("cp.async.wait_group 0;\n");
        __syncthreads();
        if (it + 1 < nK) load_stage((it + 1) & 1, (it + 1) * KST);
        char* base = smem + (it & 1) * 4 * TILEB;
        const __nv_bfloat16* ah_s = (const __nv_bfloat16*)(base + 0 * TILEB);
        const __nv_bfloat16* al_s = (const __nv_bfloat16*)(base + 1 * TILEB);
        const __nv_bfloat16* bh_s = (const __nv_bfloat16*)(base + 2 * TILEB);
        const __nv_bfloat16* bl_s = (const __nv_bfloat16*)(base + 3 * TILEB);

#pragma unroll
        for (int ks = 0; ks < KST; ks += 16) {
            unsigned ah[4][4], al[4][4], bh[4][2], bl[4][2];
#pragma unroll
            for (int mi = 0; mi < 4; ++mi) {
                int m = wm + mi * 16 + g;
                ah[mi][0] = *(const unsigned*)(ah_s + m * RSTR + ks + 2 * tig);
                ah[mi][1] = *(const unsigned*)(ah_s + (m + 8) * RSTR + ks + 2 * tig);
                ah[mi][2] = *(const unsigned*)(ah_s + m * RSTR + ks + 8 + 2 * tig);
                ah[mi][3] = *(const unsigned*)(ah_s + (m + 8) * RSTR + ks + 8 + 2 * tig);
                al[mi][0] = *(const unsigned*)(al_s + m * RSTR + ks + 2 * tig);
                al[mi][1] = *(const unsigned*)(al_s + (m + 8) * RSTR + ks + 2 * tig);
                al[mi][2] = *(const unsigned*)(al_s + m * RSTR + ks + 8 + 2 * tig);
                al[mi][3] = *(const unsigned*)(al_s + (m + 8) * RSTR + ks + 8 + 2 * tig);
            }
#pragma unroll
            for (int ni = 0; ni < 4; ++ni) {
                int n = wn + ni * 8 + g;
                bh[ni][0] = *(const unsigned*)(bh_s + n * RSTR + ks + 2 * tig);
                bh[ni][1] = *(const unsigned*)(bh_s + n * RSTR + ks + 8 + 2 * tig);
                bl[ni][0] = *(const unsigned*)(bl_s + n * RSTR + ks + 2 * tig);
                bl[ni][1] = *(const unsigned*)(bl_s + n * RSTR + ks + 8 + 2 * tig);
            }
#pragma unroll
            for (int mi = 0; mi < 4; ++mi)
#pragma unroll
                for (int ni = 0; ni < 4; ++ni) {
                    mma16(acc[mi][ni], ah[mi], bh[ni]);
                    mma16(acc[mi][ni], ah[mi], bl[ni]);
                    mma16(acc[mi][ni], al[mi], bh[ni]);
                }
        }
        __syncthreads();
    }

    // epilogue
#pragma unroll
    for (int mi = 0; mi < 4; ++mi) {
        int r0 = brow + wm + mi * 16 + g;
#pragma unroll
        for (int ni = 0; ni < 4; ++ni) {
            int c0 = bcol + wn + ni * 8 + 2 * tig;
            if (mode == 0) {
                float* Cz = C + (long)blockIdx.z * cSlab;
                if (r0 < M)
                    *(float2*)(Cz + (long)r0 * ldc + c0) =
                        make_float2(acc[mi][ni][0], acc[mi][ni][1]);
                if (r0 + 8 < M)
                    *(float2*)(Cz + (long)(r0 + 8) * ldc + c0) =
                        make_float2(acc[mi][ni][2], acc[mi][ni][3]);
            } else if (mode == 1) {
                int b = c0 >> 8, s0 = c0 & 255;
                float d0 = dvec[c0], d1 = dvec[c0 + 1];
                long baseO = (long)b * NNODES * SDIM;
                if (r0 < M)
                    store_split(Ohi, Olo, baseO + (long)r0 * SDIM + s0,
                                acc[mi][ni][0] + d0, acc[mi][ni][1] + d1);
                if (r0 + 8 < M)
                    store_split(Ohi, Olo, baseO + (long)(r0 + 8) * SDIM + s0,
                                acc[mi][ni][2] + d0, acc[mi][ni][3] + d1);
            } else {
                if (r0 < M)
                    store_split(Ohi, Olo, (long)r0 * ldc + c0,
                                acc[mi][ni][0], acc[mi][ni][1]);
                if (r0 + 8 < M)
                    store_split(Ohi, Olo, (long)(r0 + 8) * ldc + c0,
                                acc[mi][ni][2], acc[mi][ni][3]);
            }
        }
    }
}

// ---------------- CSR aggregation + bias + leaky relu, split output --------
__global__ __launch_bounds__(256) void k_agg(const float* __restrict__ bias) {
    int node = blockIdx.x * 4 + (threadIdx.x >> 6);
    int b = blockIdx.y;
    int tid = threadIdx.x & 63;
    float dt = g_dinv[node];
    long base4 = (long)b * NNODES * (SDIM / 4);
    const float4* hB4 = (const float4*)g_hB + base4;

    float4 v = hB4[(long)node * 64 + tid];
    float sw = dt * dt;
    float4 acc = make_float4(v.x * sw, v.y * sw, v.z * sw, v.w * sw);
    int e0 = g_off[node], e1 = g_off[node + 1];
    for (int e = e0; e < e1; ++e) {
        int src = g_srcs[e];
        float w = g_dinv[src] * dt;
        float4 u = hB4[(long)src * 64 + tid];
        acc.x = fmaf(u.x, w, acc.x);
        acc.y = fmaf(u.y, w, acc.y);
        acc.z = fmaf(u.z, w, acc.z);
        acc.w = fmaf(u.w, w, acc.w);
    }
    float4 bb = ((const float4*)bias)[tid];
    acc.x += bb.x; acc.y += bb.y; acc.z += bb.z; acc.w += bb.w;
    acc.x = acc.x > 0.f ? acc.x : 0.01f * acc.x;
    acc.y = acc.y > 0.f ? acc.y : 0.01f * acc.y;
    acc.z = acc.z > 0.f ? acc.z : 0.01f * acc.z;
    acc.w = acc.w > 0.f ? acc.w : 0.01f * acc.w;

    long baseE = (long)b * NNODES * SDIM + (long)node * SDIM + tid * 4;
    __nv_bfloat16 h0, l0, h1, l1, h2, l2, h3, l3;
    bsplit(acc.x, h0, l0); bsplit(acc.y, h1, l1);
    bsplit(acc.z, h2, l2); bsplit(acc.w, h3, l3);
    __nv_bfloat162* ph = (__nv_bfloat162*)(g_Ahi + baseE);
    __nv_bfloat162* pl = (__nv_bfloat162*)(g_Alo + baseE);
    ph[0] = __nv_bfloat162{h0, h1}; ph[1] = __nv_bfloat162{h2, h3};
    pl[0] = __nv_bfloat162{l0, l1}; pl[1] = __nv_bfloat162{l2, l3};
}

// ---------------- output ---------------------------------------------------
__global__ void k_out(const float* __restrict__ wbp, const float* __restrict__ bbp,
                      float* __restrict__ out) {
    int gw = (blockIdx.x * blockDim.x + threadIdx.x) >> 5;
    int lane = threadIdx.x & 31;
    if (gw >= NB * NNODES) return;
    int b = gw / NNODES, n = gw % NNODES;
    long off = ((long)b * NNODES + n) * SDIM;
    const __nv_bfloat162* h2 = (const __nv_bfloat162*)(g_Ahi + off);
    const __nv_bfloat162* l2 = (const __nv_bfloat162*)(g_Alo + off);
    const float2* w2 = (const float2*)wbp;
    float s = 0.f;
#pragma unroll
    for (int k = lane; k < SDIM / 2; k += 32) {
        float2 hh = __bfloat1622float2(h2[k]);
        float2 ll = __bfloat1622float2(l2[k]);
        float2 ww = w2[k];
        s = fmaf(hh.x + ll.x, ww.x, s);
        s = fmaf(hh.y + ll.y, ww.y, s);
    }
#pragma unroll
    for (int o = 16; o; o >>= 1) s += __shfl_xor_sync(0xffffffffu, s, o);
    if (lane == 0) out[(long)b * NNODES + n] = s + bbp[0];
}

// ---------------- launcher -------------------------------------------------
extern "C" void kernel_launch(void* const* d_in, const int* in_sizes, int n_in,
                              void* d_out, int out_size) {
    const float* x     = (const float*)d_in[0];
    const float* nodes = (const float*)d_in[1];
    const int*   ei    = (const int*)  d_in[2];
    const float* Wp    = (const float*)d_in[3];
    const float* bp    = (const float*)d_in[4];
    const float* gW    = (const float*)d_in[5];
    const float* gb    = (const float*)d_in[6];
    const float* wbp   = (const float*)d_in[7];
    const float* bbp   = (const float*)d_in[8];
    float* out = (float*)d_out;

    cudaFuncSetAttribute(mma_bf, cudaFuncAttributeMaxDynamicSharedMemorySize, MMA_SMEM);

    void *pNh, *pNl, *pXh, *pXl, *pWh, *pWl, *pCh, *pCl, *pTh, *pTl, *pAh, *pAl, *pHB, *pDV;
    cudaGetSymbolAddress(&pNh, g_nsum_hi); cudaGetSymbolAddress(&pNl, g_nsum_lo);
    cudaGetSymbolAddress(&pXh, g_x_hi);    cudaGetSymbolAddress(&pXl, g_x_lo);
    cudaGetSymbolAddress(&pWh, g_WpT_hi);  cudaGetSymbolAddress(&pWl, g_WpT_lo);
    cudaGetSymbolAddress(&pCh, g_CT_hi);   cudaGetSymbolAddress(&pCl, g_CT_lo);
    cudaGetSymbolAddress(&pTh, g_WT_hi);   cudaGetSymbolAddress(&pTl, g_WT_lo);
    cudaGetSymbolAddress(&pAh, g_Ahi);     cudaGetSymbolAddress(&pAl, g_Alo);
    cudaGetSymbolAddress(&pHB, g_hB);      cudaGetSymbolAddress(&pDV, g_dvec);

    const int MB = (NNODES + 127) / 128;   // 157
    const long slab = (long)NNODES * SDIM;

    // 0: nsum -> hi/lo
    k_nsum<<<(int)(((long)NNODES * FDIM / 4 + 255) / 256), 256>>>(nodes);
    // 1: x cvt + WpT + WT + dvec
    k_prep<<<PREP_S0 + PREP_S1 + PREP_S2 + BSJ, 256>>>(x, Wp, gW, bp);
    // 2: CT = x @ Wp (mode 2, split out, ldc = FDIM)
    mma_bf<<<dim3(BSJ / 128, FDIM / 128, 1), 256, MMA_SMEM>>>(
        (__nv_bfloat16*)pXh, (__nv_bfloat16*)pXl,
        (__nv_bfloat16*)pWh, (__nv_bfloat16*)pWl,
        nullptr, (__nv_bfloat16*)pCh, (__nv_bfloat16*)pCl, nullptr,
        BSJ, FDIM, FDIM, 0, 0, 2);
    // 3: H0 = nsum @ CT^T + dvec (mode 1)  <- ncu samples launch index 3
    mma_bf<<<dim3(MB, BSJ / 128, 1), 256, MMA_SMEM>>>(
        (__nv_bfloat16*)pNh, (__nv_bfloat16*)pNl,
        (__nv_bfloat16*)pCh, (__nv_bfloat16*)pCl,
        nullptr, (__nv_bfloat16*)pAh, (__nv_bfloat16*)pAl, (float*)pDV,
        NNODES, FDIM, 0, 0, 0, 1);

    // CSR build
    k_init_deg<<<(NNODES + 255) / 256, 256>>>();
    k_hist<<<(NE_ + 255) / 256, 256>>>(ei);
    k_scan<<<1, 512>>>();
    k_scatter<<<(NE_ + 255) / 256, 256>>>(ei);

    // GCN layers
    for (int l = 0; l < NLAYERS; ++l) {
        mma_bf<<<dim3(MB, SDIM / 128, NB), 256, MMA_SMEM>>>(
            (__nv_bfloat16*)pAh, (__nv_bfloat16*)pAl,
            (__nv_bfloat16*)pTh + (long)l * SDIM * SDIM,
            (__nv_bfloat16*)pTl + (long)l * SDIM * SDIM,
            (float*)pHB, nullptr, nullptr, nullptr,
            NNODES, SDIM, SDIM, slab, slab, 0);
        k_agg<<<dim3(NNODES / 4, NB), 256>>>(gb + (long)l * SDIM);
    }

    // belief projection
    k_out<<<(NB * NNODES * 32 + 255) / 256, 256>>>(wbp, bbp, out);
}